// round 8
// baseline (speedup 1.0000x reference)
#include <cuda_runtime.h>

#define DIMC 192
#define BB   4
#define HH   256
#define WW   256
#define RR   48
#define KK9  9
#define EPSV 1e-5f
#define NCTA   592          // 4 x 148: exactly 4 CTAs per SM, zero imbalance
#define NPLANE (BB * DIMC)  // 768

// Scratch (allocation-free rule: __device__ globals; zero-initialized)
__device__ float g_pooled[NPLANE];
__device__ unsigned g_pool_next;
__device__ unsigned g_conv_next;
__device__ unsigned g_arrive;
__device__ unsigned g_done;

// ---- 256-bit L2 eviction-hinted accesses ----------------------------------
__device__ __forceinline__ void ld256_evict_last(const float* p, float* v) {
    asm volatile("ld.global.L2::evict_last.v8.b32 {%0,%1,%2,%3,%4,%5,%6,%7}, [%8];"
                 : "=f"(v[0]), "=f"(v[1]), "=f"(v[2]), "=f"(v[3]),
                   "=f"(v[4]), "=f"(v[5]), "=f"(v[6]), "=f"(v[7])
                 : "l"(p));
}
__device__ __forceinline__ void ld256_evict_first(const float* p, float* v) {
    asm volatile("ld.global.L2::evict_first.v8.b32 {%0,%1,%2,%3,%4,%5,%6,%7}, [%8];"
                 : "=f"(v[0]), "=f"(v[1]), "=f"(v[2]), "=f"(v[3]),
                   "=f"(v[4]), "=f"(v[5]), "=f"(v[6]), "=f"(v[7])
                 : "l"(p));
}
__device__ __forceinline__ void st256_evict_first(float* p, const float* v) {
    asm volatile("st.global.L2::evict_first.v8.b32 [%0], {%1,%2,%3,%4,%5,%6,%7,%8};"
                 :: "l"(p),
                    "f"(v[0]), "f"(v[1]), "f"(v[2]), "f"(v[3]),
                    "f"(v[4]), "f"(v[5]), "f"(v[6]), "f"(v[7])
                 : "memory");
}

// ---------------------------------------------------------------------------
// Fused persistent kernel with work stealing:
//   pool jobs (ascending planes) -> grid barrier -> MLP -> conv jobs
//   (descending planes: most recently pooled = hottest in L2, consumed first)
// 592 CTAs x 256 thr; launch_bounds(256,4) => all CTAs resident (4/SM exact).
// ---------------------------------------------------------------------------
__global__ __launch_bounds__(256, 4) void fused_kernel(
    const float* __restrict__ x,
    const float* __restrict__ w1,
    const float* __restrict__ gamma,
    const float* __restrict__ beta,
    const float* __restrict__ rmean,
    const float* __restrict__ rvar,
    const float* __restrict__ w2,
    const float* __restrict__ b2,
    const float* __restrict__ bias,
    float* __restrict__ out) {

    const int tid  = threadIdx.x;
    const int warp = tid >> 5;
    const int lane = tid & 31;

    __shared__ float tsh[BB * RR];   // hidden vectors for all 4 batches
    __shared__ float wsh[4];         // 4 live taps of current conv plane
    __shared__ float red[8];         // pool reduction scratch
    __shared__ unsigned job_sh;

    // ---------------- Phase 1: pool jobs (evict_last pins x in L2) ---------
    for (;;) {
        if (tid == 0) job_sh = atomicAdd(&g_pool_next, 1u);
        __syncthreads();
        const unsigned plane = job_sh;
        __syncthreads();
        if (plane >= NPLANE) break;

        const float* __restrict__ p = x + (size_t)plane * HH * WW;
        float s = 0.f;
        #pragma unroll 4
        for (int i = tid; i < (HH * WW) / 8; i += 256) {
            float v[8];
            ld256_evict_last(p + i * 8, v);
            s += ((v[0] + v[1]) + (v[2] + v[3])) + ((v[4] + v[5]) + (v[6] + v[7]));
        }
        #pragma unroll
        for (int o = 16; o > 0; o >>= 1) s += __shfl_down_sync(0xffffffffu, s, o);
        if (lane == 0) red[warp] = s;
        __syncthreads();
        if (tid < 8) {
            float v = red[tid];
            #pragma unroll
            for (int o = 4; o > 0; o >>= 1) v += __shfl_down_sync(0xffu, v, o);
            if (tid == 0) g_pooled[plane] = v * (1.0f / (HH * WW));
        }
        __syncthreads();
    }

    // ---------------- Grid-wide barrier ------------------------------------
    if (tid == 0) {
        __threadfence();
        atomicAdd(&g_arrive, 1u);
        while (*(volatile unsigned*)&g_arrive < (unsigned)NCTA) { __nanosleep(64); }
        __threadfence();
    }
    __syncthreads();

    // ---------------- Phase 2: hidden vectors for all 4 batches ------------
    if (tid < BB * RR) {
        const int b = tid / RR, j = tid % RR;
        const float* __restrict__ pb = &g_pooled[b * DIMC];
        const float* __restrict__ wj = &w1[j * DIMC];
        float acc = 0.f;
        #pragma unroll 8
        for (int c = 0; c < DIMC; c++) acc = fmaf(pb[c], wj[c], acc);
        acc = gamma[j] * (acc - rmean[j]) * rsqrtf(rvar[j] + EPSV) + beta[j];
        tsh[tid] = fmaxf(acc, 0.f);
    }
    __syncthreads();

    // ---------------- Phase 3: conv jobs, descending plane order -----------
    for (;;) {
        if (tid == 0) job_sh = atomicAdd(&g_conv_next, 1u);
        __syncthreads();
        const unsigned job = job_sh;
        if (job >= NPLANE) break;
        const int plane = NPLANE - 1 - (int)job;  // hottest-in-L2 first
        const int b = plane / DIMC;
        const int c = plane % DIMC;

        // 4 live taps: kidx 0..3 = (0,0),(0,1),(0,2),(1,0)
        if (tid < 4) {
            const int o = c * KK9 + tid;
            float acc = b2[o];
            const float* __restrict__ ts = &tsh[b * RR];
            const float* __restrict__ wr = &w2[(size_t)o * RR];
            #pragma unroll
            for (int j = 0; j < RR; j++) acc = fmaf(ts[j], wr[j], acc);
            wsh[tid] = acc;
        }
        __syncthreads();
        const float w00 = wsh[0], w01 = wsh[1], w02 = wsh[2], w10 = wsh[3];
        const float bvv = bias[c];

        const float* __restrict__ in = x + (size_t)plane * HH * WW;
        float* __restrict__ op = out + (size_t)plane * HH * WW;

        const int col0 = lane * 8;      // 32 lanes x 8 cols = full row
        const int y0   = warp * 32;     // 8 warps x 32 rows

        float p[8];
        float pm1, pp8;
        if (warp == 0) {
            #pragma unroll
            for (int i = 0; i < 8; i++) p[i] = 0.f;
            pm1 = 0.f; pp8 = 0.f;
        } else {
            ld256_evict_first(in + (y0 - 1) * WW + col0, p);
            pm1 = __shfl_up_sync(0xffffffffu, p[7], 1);
            if (lane == 0) pm1 = 0.f;
            pp8 = __shfl_down_sync(0xffffffffu, p[0], 1);
            if (lane == 31) pp8 = 0.f;
        }

        #pragma unroll 4
        for (int y = y0; y < y0 + 32; y++) {
            float cv[8];
            ld256_evict_first(in + y * WW + col0, cv);

            float cm1 = __shfl_up_sync(0xffffffffu, cv[7], 1);
            if (lane == 0) cm1 = 0.f;

            float o[8];
            o[0] = fmaf(w00, pm1,  fmaf(w01, p[0], fmaf(w02, p[1], fmaf(w10, cm1, bvv))));
            #pragma unroll
            for (int i = 1; i < 7; i++)
                o[i] = fmaf(w00, p[i-1], fmaf(w01, p[i], fmaf(w02, p[i+1], fmaf(w10, cv[i-1], bvv))));
            o[7] = fmaf(w00, p[6], fmaf(w01, p[7], fmaf(w02, pp8, fmaf(w10, cv[6], bvv))));

            st256_evict_first(op + y * WW + col0, o);

            float nx = __shfl_down_sync(0xffffffffu, cv[0], 1);
            if (lane == 31) nx = 0.f;
            pm1 = cm1;
            pp8 = nx;
            #pragma unroll
            for (int i = 0; i < 8; i++) p[i] = cv[i];
        }
        __syncthreads();   // protect wsh before next job overwrites it
    }

    // ---------------- Reset counters for next graph replay -----------------
    if (tid == 0) {
        unsigned d = atomicAdd(&g_done, 1u);
        if (d == (unsigned)(NCTA - 1)) {
            g_pool_next = 0u;
            g_conv_next = 0u;
            g_arrive    = 0u;
            g_done      = 0u;
            __threadfence();
        }
    }
}

// ---------------------------------------------------------------------------
// Launch. Inputs (metadata order):
//  0:x 1:w1 2:gamma 3:beta 4:running_mean 5:running_var 6:w2 7:b2 8:bias
// ---------------------------------------------------------------------------
extern "C" void kernel_launch(void* const* d_in, const int* in_sizes, int n_in,
                              void* d_out, int out_size) {
    const float* x     = (const float*)d_in[0];
    const float* w1    = (const float*)d_in[1];
    const float* gamma = (const float*)d_in[2];
    const float* beta  = (const float*)d_in[3];
    const float* rmean = (const float*)d_in[4];
    const float* rvar  = (const float*)d_in[5];
    const float* w2    = (const float*)d_in[6];
    const float* b2    = (const float*)d_in[7];
    const float* bias  = (const float*)d_in[8];
    float* out = (float*)d_out;

    fused_kernel<<<NCTA, 256>>>(x, w1, gamma, beta, rmean, rvar, w2, b2, bias, out);
}

// round 9
// speedup vs baseline: 1.0691x; 1.0691x over previous
#include <cuda_runtime.h>

#define DIMC 192
#define BB   4
#define HH   256
#define WW   256
#define RR   48
#define KK9  9
#define EPSV 1e-5f
#define NCTA   296              // 2 x 148: exactly 2 CTAs per SM, all resident
#define NPLANE (BB * DIMC)      // 768
#define CH     32               // rows per chunk
#define CHUNKS (HH / CH)        // 8 chunks per plane
#define NJOB   (NPLANE * CHUNKS)// 6144 jobs per phase

// Scratch (allocation-free rule: __device__ globals; zero-initialized)
__device__ float g_part[NJOB];      // per-chunk partial sums (deterministic)
__device__ unsigned g_arrive;
__device__ unsigned g_done;

// ---- 256-bit L2 eviction-hinted accesses ----------------------------------
__device__ __forceinline__ void ld256_evict_last(const float* p, float* v) {
    asm volatile("ld.global.L2::evict_last.v8.b32 {%0,%1,%2,%3,%4,%5,%6,%7}, [%8];"
                 : "=f"(v[0]), "=f"(v[1]), "=f"(v[2]), "=f"(v[3]),
                   "=f"(v[4]), "=f"(v[5]), "=f"(v[6]), "=f"(v[7])
                 : "l"(p));
}
__device__ __forceinline__ void ld256_evict_first(const float* p, float* v) {
    asm volatile("ld.global.L2::evict_first.v8.b32 {%0,%1,%2,%3,%4,%5,%6,%7}, [%8];"
                 : "=f"(v[0]), "=f"(v[1]), "=f"(v[2]), "=f"(v[3]),
                   "=f"(v[4]), "=f"(v[5]), "=f"(v[6]), "=f"(v[7])
                 : "l"(p));
}
__device__ __forceinline__ void st256_evict_first(float* p, const float* v) {
    asm volatile("st.global.L2::evict_first.v8.b32 [%0], {%1,%2,%3,%4,%5,%6,%7,%8};"
                 :: "l"(p),
                    "f"(v[0]), "f"(v[1]), "f"(v[2]), "f"(v[3]),
                    "f"(v[4]), "f"(v[5]), "f"(v[6]), "f"(v[7])
                 : "memory");
}

// ---------------------------------------------------------------------------
// Fused persistent kernel, static fine-grained partition:
//   pool chunk-jobs (ascending) -> grid barrier -> reduce+MLP -> conv
//   chunk-jobs (descending: most recently pooled = L2-hottest first).
// 296 CTAs x 256 thr; launch_bounds(256,2) => exactly 2 CTAs/SM, one wave.
// Job quantum = 32 rows of one plane => 6144 jobs, <=1 job imbalance.
// ---------------------------------------------------------------------------
__global__ __launch_bounds__(256, 2) void fused_kernel(
    const float* __restrict__ x,
    const float* __restrict__ w1,
    const float* __restrict__ gamma,
    const float* __restrict__ beta,
    const float* __restrict__ rmean,
    const float* __restrict__ rvar,
    const float* __restrict__ w2,
    const float* __restrict__ b2,
    const float* __restrict__ bias,
    float* __restrict__ out) {

    const int tid  = threadIdx.x;
    const int warp = tid >> 5;
    const int lane = tid & 31;
    const int cta  = blockIdx.x;

    __shared__ float pooled_sh[NPLANE];  // 3 KB: per-plane means
    __shared__ float tsh[BB * RR];       // hidden vectors, all 4 batches
    __shared__ float wsh[4];             // live taps of current conv job
    __shared__ float red[8];             // reduction scratch

    // number of jobs in this CTA's interleaved list
    const int nmy = (cta < (NJOB % NCTA)) ? (NJOB / NCTA + 1) : (NJOB / NCTA);

    // ---------------- Phase 1: pool partial sums (evict_last pins x) -------
    for (int i = 0; i < nmy; i++) {
        const int j     = cta + i * NCTA;        // ascending in time
        const int plane = j >> 3;                // j / CHUNKS
        const int chunk = j & 7;
        const float* __restrict__ p =
            x + (size_t)plane * HH * WW + (size_t)chunk * CH * WW;

        float s = 0.f;
        // CH*WW = 8192 floats = 1024 float8 / 256 threads = 4 iters
        #pragma unroll
        for (int it = 0; it < 4; it++) {
            float v[8];
            ld256_evict_last(p + (it * 256 + tid) * 8, v);
            s += ((v[0] + v[1]) + (v[2] + v[3])) + ((v[4] + v[5]) + (v[6] + v[7]));
        }
        #pragma unroll
        for (int o = 16; o > 0; o >>= 1) s += __shfl_down_sync(0xffffffffu, s, o);
        if (lane == 0) red[warp] = s;
        __syncthreads();
        if (tid < 8) {
            float v = red[tid];
            #pragma unroll
            for (int o = 4; o > 0; o >>= 1) v += __shfl_down_sync(0xffu, v, o);
            if (tid == 0) g_part[j] = v;
        }
        __syncthreads();
    }

    // ---------------- Grid-wide barrier ------------------------------------
    if (tid == 0) {
        __threadfence();
        atomicAdd(&g_arrive, 1u);
        while (*(volatile unsigned*)&g_arrive < (unsigned)NCTA) { __nanosleep(64); }
        __threadfence();
    }
    __syncthreads();

    // ---------------- Phase 2: deterministic reduce + hidden vectors -------
    for (int p = tid; p < NPLANE; p += 256) {
        const float* __restrict__ pp = &g_part[p * CHUNKS];
        float s = ((pp[0] + pp[1]) + (pp[2] + pp[3]))
                + ((pp[4] + pp[5]) + (pp[6] + pp[7]));   // fixed order
        pooled_sh[p] = s * (1.0f / (HH * WW));
    }
    __syncthreads();
    if (tid < BB * RR) {
        const int b = tid / RR, jj = tid % RR;
        const float* __restrict__ pb = &pooled_sh[b * DIMC];
        const float* __restrict__ wj = &w1[jj * DIMC];
        float acc = 0.f;
        #pragma unroll 8
        for (int c = 0; c < DIMC; c++) acc = fmaf(pb[c], wj[c], acc);
        acc = gamma[jj] * (acc - rmean[jj]) * rsqrtf(rvar[jj] + EPSV) + beta[jj];
        tsh[tid] = fmaxf(acc, 0.f);
    }
    __syncthreads();

    // ---------------- Phase 3: conv chunk-jobs, descending (L2-hot first) --
    for (int i = nmy - 1; i >= 0; i--) {
        const int j     = cta + i * NCTA;
        const int plane = j >> 3;
        const int chunk = j & 7;
        const int b     = plane / DIMC;
        const int c     = plane % DIMC;

        // 4 live taps: kidx 0..3 = (0,0),(0,1),(0,2),(1,0)
        if (tid < 4) {
            const int o = c * KK9 + tid;
            float acc = b2[o];
            const float* __restrict__ ts = &tsh[b * RR];
            const float* __restrict__ wr = &w2[(size_t)o * RR];
            #pragma unroll
            for (int k = 0; k < RR; k++) acc = fmaf(ts[k], wr[k], acc);
            wsh[tid] = acc;
        }
        __syncthreads();
        const float w00 = wsh[0], w01 = wsh[1], w02 = wsh[2], w10 = wsh[3];
        const float bvv = bias[c];

        const float* __restrict__ in = x + (size_t)plane * HH * WW;
        float* __restrict__ op = out + (size_t)plane * HH * WW;

        const int col0 = lane * 8;              // 32 lanes x 8 cols = full row
        const int y0   = chunk * CH + warp * 4; // each warp: 4 consecutive rows

        // previous-row state (halo)
        float p[8];
        float pm1, pp8;
        if (y0 == 0) {
            #pragma unroll
            for (int q = 0; q < 8; q++) p[q] = 0.f;
            pm1 = 0.f; pp8 = 0.f;
        } else {
            ld256_evict_first(in + (y0 - 1) * WW + col0, p);
            pm1 = __shfl_up_sync(0xffffffffu, p[7], 1);
            if (lane == 0) pm1 = 0.f;
            pp8 = __shfl_down_sync(0xffffffffu, p[0], 1);
            if (lane == 31) pp8 = 0.f;
        }

        #pragma unroll
        for (int r = 0; r < 4; r++) {
            const int y = y0 + r;
            float cv[8];
            ld256_evict_first(in + y * WW + col0, cv);

            float cm1 = __shfl_up_sync(0xffffffffu, cv[7], 1);
            if (lane == 0) cm1 = 0.f;

            float o[8];
            o[0] = fmaf(w00, pm1,  fmaf(w01, p[0], fmaf(w02, p[1], fmaf(w10, cm1, bvv))));
            #pragma unroll
            for (int q = 1; q < 7; q++)
                o[q] = fmaf(w00, p[q-1], fmaf(w01, p[q], fmaf(w02, p[q+1], fmaf(w10, cv[q-1], bvv))));
            o[7] = fmaf(w00, p[6], fmaf(w01, p[7], fmaf(w02, pp8, fmaf(w10, cv[6], bvv))));

            st256_evict_first(op + y * WW + col0, o);

            float nx = __shfl_down_sync(0xffffffffu, cv[0], 1);
            if (lane == 31) nx = 0.f;
            pm1 = cm1;
            pp8 = nx;
            #pragma unroll
            for (int q = 0; q < 8; q++) p[q] = cv[q];
        }
        __syncthreads();   // protect wsh before next job overwrites it
    }

    // ---------------- Reset counters for next graph replay -----------------
    if (tid == 0) {
        unsigned d = atomicAdd(&g_done, 1u);
        if (d == (unsigned)(NCTA - 1)) {
            g_arrive = 0u;
            g_done   = 0u;
            __threadfence();
        }
    }
}

// ---------------------------------------------------------------------------
// Launch. Inputs (metadata order):
//  0:x 1:w1 2:gamma 3:beta 4:running_mean 5:running_var 6:w2 7:b2 8:bias
// ---------------------------------------------------------------------------
extern "C" void kernel_launch(void* const* d_in, const int* in_sizes, int n_in,
                              void* d_out, int out_size) {
    const float* x     = (const float*)d_in[0];
    const float* w1    = (const float*)d_in[1];
    const float* gamma = (const float*)d_in[2];
    const float* beta  = (const float*)d_in[3];
    const float* rmean = (const float*)d_in[4];
    const float* rvar  = (const float*)d_in[5];
    const float* w2    = (const float*)d_in[6];
    const float* b2    = (const float*)d_in[7];
    const float* bias  = (const float*)d_in[8];
    float* out = (float*)d_out;

    fused_kernel<<<NCTA, 256>>>(x, w1, gamma, beta, rmean, rvar, w2, b2, bias, out);
}